// round 6
// baseline (speedup 1.0000x reference)
#include <cuda_runtime.h>

// f (32,512,512) f32, K (5,5,512,512) f32, dt (32,) -> out = relu(f + dt * conv_unshared5x5(f, K))
#define BATCH 32
#define H 512
#define W 512
#define HW (H * W)
#define HALO 2

// Block: 128 threads = 32 tx * 4 ty. Each thread computes a 2x2 pixel patch
// (XV=2, VY=2) for 4 batches (float4) -> tile 64 x 8 per block, grid (8,64)=512.
// f staged in smem split into even-x / odd-x float4(batch) arrays so the
// stride-2 x windows become stride-1 (conflict-free). GSTAGE=4 groups (16
// batches) per stage, 2 stages.
#define TILE_X 64
#define TILE_Y 8
#define SM_ROWS 12               // TILE_Y + 2*HALO
#define XHALO (TILE_X + 2 * HALO)  // 68
#define ECOLS 34                 // even (or odd) x positions per row
#define NPOS (SM_ROWS * XHALO)   // 816
#define GSTAGE 4                 // 4 groups of 4 batches per stage
#define NSTAGE 2
#define EO_ELEMS (GSTAGE * SM_ROWS * ECOLS)  // 1632 float4 per parity array

#define FMA4(acc, fv, kk)              \
    acc.x = fmaf(fv.x, kk, acc.x);     \
    acc.y = fmaf(fv.y, kk, acc.y);     \
    acc.z = fmaf(fv.z, kk, acc.z);     \
    acc.w = fmaf(fv.w, kk, acc.w);

__global__ __launch_bounds__(128, 4) void op2d_kernel(
    const float* __restrict__ f,
    const float* __restrict__ Kk,
    const float* __restrict__ dt,
    float* __restrict__ out)
{
    // [even array][64B pad for 16-bank shift][odd array]
    __shared__ float4 buf[2 * EO_ELEMS + 4];   // 52352 B
    __shared__ __align__(16) float dts[BATCH];

    const int tid = threadIdx.x;
    const int tx = tid & 31;
    const int ty = tid >> 5;
    const int tileX = blockIdx.x * TILE_X;
    const int tileY = blockIdx.y * TILE_Y;

    if (tid < BATCH) dts[tid] = dt[tid];

    const int x0 = tileX + 2 * tx;   // thread's left pixel column (even)
    const int y0 = tileY + 2 * ty;   // thread's top pixel row
    const int ry = 2 * ty;

    const int OODD = EO_ELEMS + 4;   // odd-array base offset (16-bank shifted)

    #pragma unroll 1
    for (int s = 0; s < NSTAGE; s++) {
        __syncthreads();             // previous stage's compute done

        // ---- Stage 16 batches into even/odd smem arrays ----
        const int b0 = s * (GSTAGE * 4);
        #pragma unroll
        for (int it = 0; it < 7; it++) {   // ceil(816/128)
            const int p = tid + it * 128;
            if (p < NPOS) {
                const int r  = p / XHALO;
                const int cx = p - r * XHALO;
                const int gy = tileY + r - HALO;
                const int gx = tileX + cx - HALO;
                const bool in = ((unsigned)gy < (unsigned)H) & ((unsigned)gx < (unsigned)W);
                const float* fp = f + (b0 * HW + gy * W + gx);
                const int base = ((cx & 1) ? OODD : 0) + r * ECOLS + (cx >> 1);
                #pragma unroll
                for (int g = 0; g < GSTAGE; g++) {
                    float4 v;
                    v.x = in ? fp[(g * 4 + 0) * HW] : 0.0f;
                    v.y = in ? fp[(g * 4 + 1) * HW] : 0.0f;
                    v.z = in ? fp[(g * 4 + 2) * HW] : 0.0f;
                    v.w = in ? fp[(g * 4 + 3) * HW] : 0.0f;
                    buf[base + g * (SM_ROWS * ECOLS)] = v;
                }
            }
        }
        __syncthreads();

        // ---- Compute: 2 passes of 2 groups; K taps (float2 over x0,x1) shared
        //      across the pass's groups ----
        #pragma unroll 1
        for (int h = 0; h < 2; h++) {
            // accumulators: [group-in-pass][pixel]: e=x0, o=x1; 0=y0, 1=y1
            float4 aE0[2], aO0[2], aE1[2], aO1[2];
            #pragma unroll
            for (int gp = 0; gp < 2; gp++) {
                aE0[gp] = make_float4(0.f, 0.f, 0.f, 0.f);
                aO0[gp] = make_float4(0.f, 0.f, 0.f, 0.f);
                aE1[gp] = make_float4(0.f, 0.f, 0.f, 0.f);
                aO1[gp] = make_float4(0.f, 0.f, 0.f, 0.f);
            }

            #pragma unroll
            for (int r = 0; r < 6; r++) {
                float2 k0[5], k1[5];
                if (r < 5) {
                    #pragma unroll
                    for (int j = 0; j < 5; j++)
                        k0[j] = __ldg((const float2*)&Kk[((r * 5 + j) * H + y0) * W + x0]);
                }
                if (r >= 1) {
                    #pragma unroll
                    for (int j = 0; j < 5; j++)
                        k1[j] = __ldg((const float2*)&Kk[(((r - 1) * 5 + j) * H + y0 + 1) * W + x0]);
                }
                #pragma unroll
                for (int gp = 0; gp < 2; gp++) {
                    const int g = 2 * h + gp;
                    const int rb = (g * SM_ROWS + ry + r) * ECOLS;
                    float4 fe0 = buf[rb + tx];
                    float4 fe1 = buf[rb + tx + 1];
                    float4 fe2 = buf[rb + tx + 2];
                    float4 fo0 = buf[OODD + rb + tx];
                    float4 fo1 = buf[OODD + rb + tx + 1];
                    float4 fo2 = buf[OODD + rb + tx + 2];
                    // x0 taps: fe0 fo0 fe1 fo1 fe2 ; x1 taps: fo0 fe1 fo1 fe2 fo2
                    if (r < 5) {
                        FMA4(aE0[gp], fe0, k0[0].x); FMA4(aO0[gp], fo0, k0[0].y);
                        FMA4(aE0[gp], fo0, k0[1].x); FMA4(aO0[gp], fe1, k0[1].y);
                        FMA4(aE0[gp], fe1, k0[2].x); FMA4(aO0[gp], fo1, k0[2].y);
                        FMA4(aE0[gp], fo1, k0[3].x); FMA4(aO0[gp], fe2, k0[3].y);
                        FMA4(aE0[gp], fe2, k0[4].x); FMA4(aO0[gp], fo2, k0[4].y);
                    }
                    if (r >= 1) {
                        FMA4(aE1[gp], fe0, k1[0].x); FMA4(aO1[gp], fo0, k1[0].y);
                        FMA4(aE1[gp], fo0, k1[1].x); FMA4(aO1[gp], fe1, k1[1].y);
                        FMA4(aE1[gp], fe1, k1[2].x); FMA4(aO1[gp], fo1, k1[2].y);
                        FMA4(aE1[gp], fo1, k1[3].x); FMA4(aO1[gp], fe2, k1[3].y);
                        FMA4(aE1[gp], fe2, k1[4].x); FMA4(aO1[gp], fo2, k1[4].y);
                    }
                }
            }

            // ---- Epilogue for this pass's 2 groups (8 batches) ----
            #pragma unroll
            for (int gp = 0; gp < 2; gp++) {
                const int g = 2 * h + gp;
                const int b = b0 + g * 4;
                const float4 dt4 = *(const float4*)&dts[b];
                const int rb0 = (g * SM_ROWS + ry + 2) * ECOLS + tx + 1;  // center y0
                const int rb1 = (g * SM_ROWS + ry + 3) * ECOLS + tx + 1;  // center y1
                const float4 fE0 = buf[rb0];         // f(y0, x0)
                const float4 fO0 = buf[OODD + rb0];  // f(y0, x1)
                const float4 fE1 = buf[rb1];         // f(y1, x0)
                const float4 fO1 = buf[OODD + rb1];  // f(y1, x1)

                const float* ae0 = (const float*)&aE0[gp];
                const float* ao0 = (const float*)&aO0[gp];
                const float* ae1 = (const float*)&aE1[gp];
                const float* ao1 = (const float*)&aO1[gp];
                const float* fe0p = (const float*)&fE0;
                const float* fo0p = (const float*)&fO0;
                const float* fe1p = (const float*)&fE1;
                const float* fo1p = (const float*)&fO1;
                const float* dtp  = (const float*)&dt4;

                #pragma unroll
                for (int l = 0; l < 4; l++) {
                    float2 r0, r1;
                    r0.x = fmaxf(fmaf(ae0[l], dtp[l], fe0p[l]), 0.0f);
                    r0.y = fmaxf(fmaf(ao0[l], dtp[l], fo0p[l]), 0.0f);
                    r1.x = fmaxf(fmaf(ae1[l], dtp[l], fe1p[l]), 0.0f);
                    r1.y = fmaxf(fmaf(ao1[l], dtp[l], fo1p[l]), 0.0f);
                    float* o = out + ((b + l) * H + y0) * W + x0;
                    *(float2*)o       = r0;
                    *(float2*)(o + W) = r1;
                }
            }
        }
    }
}

extern "C" void kernel_launch(void* const* d_in, const int* in_sizes, int n_in,
                              void* d_out, int out_size)
{
    const float* f  = (const float*)d_in[0];
    const float* Kk = (const float*)d_in[1];
    const float* dt = (const float*)d_in[2];
    float* out = (float*)d_out;

    dim3 grid(W / TILE_X, H / TILE_Y);  // (8, 64) = 512 blocks, one wave @ 4 CTAs/SM
    dim3 block(128);
    op2d_kernel<<<grid, block>>>(f, Kk, dt, out);
}

// round 8
// speedup vs baseline: 1.0787x; 1.0787x over previous
#include <cuda_runtime.h>

// f (32,512,512) f32, K (5,5,512,512) f32, dt (32,) -> out = relu(f + dt * conv_unshared5x5(f, K))
#define BATCH 32
#define H 512
#define W 512
#define HW (H * W)
#define HALO 2

// Tile 32x8, 128 threads (32 tx, 4 ty), VY=2 pixels/thread, batch as float4.
// 4 "pairs" of 2 batch-groups (8 batches) per tile, double-buffered in smem with
// register prefetch (software pipeline). Persistent CTAs drain 1024 tiles via an
// atomic counter (no wave-quantization tail).
#define TILE_X 32
#define TILE_Y 8
#define SM_ROWS 12
#define SM_COLS 36
#define NPOS (SM_ROWS * SM_COLS)   // 432
#define TILES_X (W / TILE_X)       // 16
#define NTILES (TILES_X * (H / TILE_Y))  // 1024
#define NPAIRS 4                   // 4 pairs x 8 batches = 32
#define PITERS 4                   // ceil(432/128)
#define GRID 740                   // 148 SMs x 5 CTAs

__device__ int g_tile_counter;

#define FMA4(acc, fv, kk)              \
    acc.x = fmaf(fv.x, kk, acc.x);     \
    acc.y = fmaf(fv.y, kk, acc.y);     \
    acc.z = fmaf(fv.z, kk, acc.z);     \
    acc.w = fmaf(fv.w, kk, acc.w);

__global__ __launch_bounds__(128, 5) void op2d_kernel(
    const float* __restrict__ f,
    const float* __restrict__ Kk,
    const float* __restrict__ dt,
    float* __restrict__ out)
{
    __shared__ float4 fs[2][2][SM_ROWS][SM_COLS];   // [pair-buffer][group] 27648 B
    __shared__ __align__(16) float dts[BATCH];
    __shared__ int s_tile;

    const int tid = threadIdx.x;
    const int tx = tid & 31;
    const int ty = tid >> 5;

    if (tid < BATCH) dts[tid] = dt[tid];

    // Tile-independent staging coordinates for this thread.
    int rr[PITERS], cc[PITERS];
    #pragma unroll
    for (int it = 0; it < PITERS; it++) {
        const int p = tid + it * 128;
        rr[it] = p / SM_COLS;
        cc[it] = p - rr[it] * SM_COLS;
    }

    float4 pf[PITERS][2];   // prefetch registers: one pair (8 batches)

    while (true) {
        if (tid == 0) s_tile = atomicAdd(&g_tile_counter, 1);
        __syncthreads();    // broadcast tile; also fences previous tile's compute
        const int tile = s_tile;
        if (tile >= NTILES) break;

        const int tileX = (tile & (TILES_X - 1)) * TILE_X;
        const int tileY = (tile >> 4) * TILE_Y;

        const int x  = tileX + tx;
        const int y0 = tileY + 2 * ty;
        const int ry = 2 * ty;
        const float* K0p = Kk + y0 * W + x;   // tap t at K0p[t*HW]
        const float* K1p = K0p + W;
        float* outp = out + y0 * W + x;

        // ---- staging helpers ----
        auto ldg_pair = [&](int pi) {
            #pragma unroll
            for (int it = 0; it < PITERS; it++) {
                if (tid + it * 128 < NPOS) {
                    const int gy = tileY + rr[it] - HALO;
                    const int gx = tileX + cc[it] - HALO;
                    const bool in = ((unsigned)gy < (unsigned)H) & ((unsigned)gx < (unsigned)W);
                    const float* fp = f + (pi * 8 * HW + gy * W + gx);
                    #pragma unroll
                    for (int g = 0; g < 2; g++) {
                        pf[it][g].x = in ? fp[(g * 4 + 0) * HW] : 0.0f;
                        pf[it][g].y = in ? fp[(g * 4 + 1) * HW] : 0.0f;
                        pf[it][g].z = in ? fp[(g * 4 + 2) * HW] : 0.0f;
                        pf[it][g].w = in ? fp[(g * 4 + 3) * HW] : 0.0f;
                    }
                }
            }
        };
        auto sts_pair = [&](int pi) {
            const int pb = pi & 1;
            #pragma unroll
            for (int it = 0; it < PITERS; it++) {
                if (tid + it * 128 < NPOS) {
                    #pragma unroll
                    for (int g = 0; g < 2; g++)
                        fs[pb][g][rr[it]][cc[it]] = pf[it][g];
                }
            }
        };

        // ---- prologue: pair0 staged, pair1 in flight ----
        ldg_pair(0);
        sts_pair(0);
        ldg_pair(1);

        #pragma unroll 1
        for (int p = 0; p < NPAIRS; p++) {
            if (p >= 1) {
                sts_pair(p);                       // pf holds pair p (loaded last iter)
                if (p + 1 < NPAIRS) ldg_pair(p + 1);  // hidden by compute of pair p
            }
            __syncthreads();                       // pair p visible to all

            // ---- compute pair p (groups 2p, 2p+1) ----
            const int pb = p & 1;
            float4 a00 = make_float4(0.f, 0.f, 0.f, 0.f);
            float4 a01 = make_float4(0.f, 0.f, 0.f, 0.f);
            float4 a10 = make_float4(0.f, 0.f, 0.f, 0.f);
            float4 a11 = make_float4(0.f, 0.f, 0.f, 0.f);

            #pragma unroll
            for (int r = 0; r < 6; r++) {
                float k0r[5], k1r[5];
                if (r < 5) {
                    #pragma unroll
                    for (int j = 0; j < 5; j++) k0r[j] = __ldg(&K0p[(r * 5 + j) * HW]);
                }
                if (r >= 1) {
                    #pragma unroll
                    for (int j = 0; j < 5; j++) k1r[j] = __ldg(&K1p[((r - 1) * 5 + j) * HW]);
                }
                #pragma unroll
                for (int j = 0; j < 5; j++) {
                    float4 fv0 = fs[pb][0][ry + r][tx + j];
                    if (r < 5)  { FMA4(a00, fv0, k0r[j]); }
                    if (r >= 1) { FMA4(a01, fv0, k1r[j]); }
                    float4 fv1 = fs[pb][1][ry + r][tx + j];
                    if (r < 5)  { FMA4(a10, fv1, k0r[j]); }
                    if (r >= 1) { FMA4(a11, fv1, k1r[j]); }
                }
            }

            // ---- epilogue: out = relu(f + dt*acc), 8 batches ----
            const int b0 = p * 8;
            #pragma unroll
            for (int g = 0; g < 2; g++) {
                const int b = b0 + g * 4;
                const float4 dt4 = *(const float4*)&dts[b];
                const float4 fc0 = fs[pb][g][ry + HALO][tx + HALO];
                const float4 fc1 = fs[pb][g][ry + HALO + 1][tx + HALO];
                const float4 p0 = (g == 0) ? a00 : a10;
                const float4 p1 = (g == 0) ? a01 : a11;

                float* o = outp + b * HW;
                o[0] = fmaxf(fmaf(p0.x, dt4.x, fc0.x), 0.0f);
                o[W] = fmaxf(fmaf(p1.x, dt4.x, fc1.x), 0.0f);
                o += HW;
                o[0] = fmaxf(fmaf(p0.y, dt4.y, fc0.y), 0.0f);
                o[W] = fmaxf(fmaf(p1.y, dt4.y, fc1.y), 0.0f);
                o += HW;
                o[0] = fmaxf(fmaf(p0.z, dt4.z, fc0.z), 0.0f);
                o[W] = fmaxf(fmaf(p1.z, dt4.z, fc1.z), 0.0f);
                o += HW;
                o[0] = fmaxf(fmaf(p0.w, dt4.w, fc0.w), 0.0f);
                o[W] = fmaxf(fmaf(p1.w, dt4.w, fc1.w), 0.0f);
            }
        }
    }
}

extern "C" void kernel_launch(void* const* d_in, const int* in_sizes, int n_in,
                              void* d_out, int out_size)
{
    const float* f  = (const float*)d_in[0];
    const float* Kk = (const float*)d_in[1];
    const float* dt = (const float*)d_in[2];
    float* out = (float*)d_out;

    void* ctr = nullptr;
    cudaGetSymbolAddress(&ctr, g_tile_counter);
    cudaMemsetAsync(ctr, 0, sizeof(int));   // capture-safe counter reset per replay

    op2d_kernel<<<GRID, 128>>>(f, Kk, dt, out);
}

// round 11
// speedup vs baseline: 1.3620x; 1.2627x over previous
#include <cuda_runtime.h>

// f (32,512,512) f32, K (5,5,512,512) f32, dt (32,) -> out = relu(f + dt * conv_unshared5x5(f, K))
#define BATCH 32
#define H 512
#define W 512
#define HW (H * W)
#define HALO 2

// Block 128 threads = 32 tx * 4 ty; each thread computes a 2x2 pixel patch
// (XV=2, VY=2) for 4 batches (float4) -> tile 64 x 8, grid (8,64)=512 = 1 wave.
// f staged in smem split even-x/odd-x so stride-2 x-windows are stride-1.
// 4 stages of 8 batches (2 float4 groups); K taps (float2 over x0,x1) loaded
// once per stage row and shared across both groups.
#define TILE_X 64
#define TILE_Y 8
#define SM_ROWS 12                  // TILE_Y + 2*HALO
#define XCOLS 68                    // TILE_X + 2*HALO
#define ECOLS 34                    // even (or odd) x positions per row
#define NPOS (SM_ROWS * XCOLS)      // 816
#define GS 2                        // groups (of 4 batches) per stage
#define NSTAGE 4
#define GSZ (SM_ROWS * ECOLS)       // 408 float4 per group per parity
#define OODD (GS * GSZ + 4)         // odd-array base (64B pad shifts banks)

#define FMA4(acc, fv, kk)              \
    acc.x = fmaf(fv.x, kk, acc.x);     \
    acc.y = fmaf(fv.y, kk, acc.y);     \
    acc.z = fmaf(fv.z, kk, acc.z);     \
    acc.w = fmaf(fv.w, kk, acc.w);

__global__ __launch_bounds__(128) void op2d_kernel(
    const float* __restrict__ f,
    const float* __restrict__ Kk,
    const float* __restrict__ dt,
    float* __restrict__ out)
{
    __shared__ float4 buf[2 * GS * GSZ + 4];   // 26176 B
    __shared__ __align__(16) float dts[BATCH];

    const int tid = threadIdx.x;
    const int tx = tid & 31;
    const int ty = tid >> 5;
    const int tileX = blockIdx.x * TILE_X;
    const int tileY = blockIdx.y * TILE_Y;

    if (tid < BATCH) dts[tid] = dt[tid];

    const int x0 = tileX + 2 * tx;   // left pixel (even)
    const int y0 = tileY + 2 * ty;   // top pixel row
    const int ry = 2 * ty;

    const float* Kp0 = Kk + y0 * W + x0;        // tap t for row y0 at Kp0[t*HW]
    const float* Kp1 = Kp0 + W;                 // tap t for row y0+1

    #pragma unroll 1
    for (int s = 0; s < NSTAGE; s++) {
        __syncthreads();             // previous stage's compute done

        // ---- Stage 8 batches into even/odd smem arrays ----
        const int b0 = s * (GS * 4);
        #pragma unroll
        for (int it = 0; it < 7; it++) {   // ceil(816/128)
            const int p = tid + it * 128;
            if (p < NPOS) {
                const int r  = p / XCOLS;
                const int cx = p - r * XCOLS;
                const int gy = tileY + r - HALO;
                const int gx = tileX + cx - HALO;
                const bool in = ((unsigned)gy < (unsigned)H) & ((unsigned)gx < (unsigned)W);
                const float* fp = f + (b0 * HW + gy * W + gx);
                const int base = ((cx & 1) ? OODD : 0) + r * ECOLS + (cx >> 1);
                #pragma unroll
                for (int g = 0; g < GS; g++) {
                    float4 v;
                    v.x = in ? fp[(g * 4 + 0) * HW] : 0.0f;
                    v.y = in ? fp[(g * 4 + 1) * HW] : 0.0f;
                    v.z = in ? fp[(g * 4 + 2) * HW] : 0.0f;
                    v.w = in ? fp[(g * 4 + 3) * HW] : 0.0f;
                    buf[base + g * GSZ] = v;
                }
            }
        }
        __syncthreads();

        // ---- Compute: both groups per stage, K taps loaded once per row ----
        // acc[group]: E0=(y0,x0) O0=(y0,x1) E1=(y1,x0) O1=(y1,x1)
        float4 aE0[GS], aO0[GS], aE1[GS], aO1[GS];
        #pragma unroll
        for (int g = 0; g < GS; g++) {
            aE0[g] = make_float4(0.f, 0.f, 0.f, 0.f);
            aO0[g] = make_float4(0.f, 0.f, 0.f, 0.f);
            aE1[g] = make_float4(0.f, 0.f, 0.f, 0.f);
            aO1[g] = make_float4(0.f, 0.f, 0.f, 0.f);
        }

        #pragma unroll
        for (int r = 0; r < 6; r++) {
            float2 k0[5], k1[5];
            if (r < 5) {
                #pragma unroll
                for (int j = 0; j < 5; j++)
                    k0[j] = __ldg((const float2*)&Kp0[(r * 5 + j) * HW]);
            }
            if (r >= 1) {
                #pragma unroll
                for (int j = 0; j < 5; j++)
                    k1[j] = __ldg((const float2*)&Kp1[((r - 1) * 5 + j) * HW]);
            }
            #pragma unroll
            for (int g = 0; g < GS; g++) {
                const float4* eb = &buf[g * GSZ + (ry + r) * ECOLS + tx];
                const float4* ob = eb + OODD;
                float4 fe0 = eb[0];
                float4 fe1 = eb[1];
                float4 fe2 = eb[2];
                float4 fo0 = ob[0];
                float4 fo1 = ob[1];
                float4 fo2 = ob[2];
                // x0 taps: fe0 fo0 fe1 fo1 fe2 ; x1 taps: fo0 fe1 fo1 fe2 fo2
                if (r < 5) {
                    FMA4(aE0[g], fe0, k0[0].x); FMA4(aO0[g], fo0, k0[0].y);
                    FMA4(aE0[g], fo0, k0[1].x); FMA4(aO0[g], fe1, k0[1].y);
                    FMA4(aE0[g], fe1, k0[2].x); FMA4(aO0[g], fo1, k0[2].y);
                    FMA4(aE0[g], fo1, k0[3].x); FMA4(aO0[g], fe2, k0[3].y);
                    FMA4(aE0[g], fe2, k0[4].x); FMA4(aO0[g], fo2, k0[4].y);
                }
                if (r >= 1) {
                    FMA4(aE1[g], fe0, k1[0].x); FMA4(aO1[g], fo0, k1[0].y);
                    FMA4(aE1[g], fo0, k1[1].x); FMA4(aO1[g], fe1, k1[1].y);
                    FMA4(aE1[g], fe1, k1[2].x); FMA4(aO1[g], fo1, k1[2].y);
                    FMA4(aE1[g], fo1, k1[3].x); FMA4(aO1[g], fe2, k1[3].y);
                    FMA4(aE1[g], fe2, k1[4].x); FMA4(aO1[g], fo2, k1[4].y);
                }
            }
        }

        // ---- Epilogue: out = relu(f + dt*acc), 8 batches ----
        #pragma unroll
        for (int g = 0; g < GS; g++) {
            const int b = b0 + g * 4;
            const float4 dt4 = *(const float4*)&dts[b];
            const int rb0 = g * GSZ + (ry + 2) * ECOLS + tx + 1;   // center y0
            const int rb1 = g * GSZ + (ry + 3) * ECOLS + tx + 1;   // center y1
            const float4 fE0 = buf[rb0];
            const float4 fO0 = buf[OODD + rb0];
            const float4 fE1 = buf[rb1];
            const float4 fO1 = buf[OODD + rb1];

            const float* ae0 = (const float*)&aE0[g];
            const float* ao0 = (const float*)&aO0[g];
            const float* ae1 = (const float*)&aE1[g];
            const float* ao1 = (const float*)&aO1[g];
            const float* fe0p = (const float*)&fE0;
            const float* fo0p = (const float*)&fO0;
            const float* fe1p = (const float*)&fE1;
            const float* fo1p = (const float*)&fO1;
            const float* dtp  = (const float*)&dt4;

            #pragma unroll
            for (int l = 0; l < 4; l++) {
                float2 r0, r1;
                r0.x = fmaxf(fmaf(ae0[l], dtp[l], fe0p[l]), 0.0f);
                r0.y = fmaxf(fmaf(ao0[l], dtp[l], fo0p[l]), 0.0f);
                r1.x = fmaxf(fmaf(ae1[l], dtp[l], fe1p[l]), 0.0f);
                r1.y = fmaxf(fmaf(ao1[l], dtp[l], fo1p[l]), 0.0f);
                float* o = out + ((b + l) * H + y0) * W + x0;
                *(float2*)o       = r0;
                *(float2*)(o + W) = r1;
            }
        }
    }
}

extern "C" void kernel_launch(void* const* d_in, const int* in_sizes, int n_in,
                              void* d_out, int out_size)
{
    const float* f  = (const float*)d_in[0];
    const float* Kk = (const float*)d_in[1];
    const float* dt = (const float*)d_in[2];
    float* out = (float*)d_out;

    dim3 grid(W / TILE_X, H / TILE_Y);  // (8, 64) = 512 blocks, single wave
    dim3 block(128);
    op2d_kernel<<<grid, block>>>(f, Kk, dt, out);
}